// round 5
// baseline (speedup 1.0000x reference)
#include <cuda_runtime.h>
#include <cuda_bf16.h>
#include <cstdint>

// ---------------------------------------------------------------------------
// RGCN conv with history cache.
//   out[n] = history_buffer[n]                       if history_map[n] != -1
//   out[n] = (1/deg) * sum_r A_r[n] @ W_r            otherwise
// Aggregate per-relation sums into compacted rows (active nodes only), split
// to bf16 hi/lo planes, then GEMM = Ah@Wh + Ah@Wl + Al@Wh with mma.sync.
// Round 5: aggregate = 2 warps/node (float2 lanes) for low regs + high MLP.
// ---------------------------------------------------------------------------

#define MAX_NODE 100000
#define PAD_ROWS (MAX_NODE + 256)
#define HID 128
#define NUM_REL 8
#define KDIM (NUM_REL * HID)   // 1024

__device__ __nv_bfloat16 g_Ah[(size_t)PAD_ROWS * KDIM];
__device__ __nv_bfloat16 g_Al[(size_t)PAD_ROWS * KDIM];
__device__ __nv_bfloat16 g_Wh[(size_t)HID * KDIM];   // [n][k] (K-major)
__device__ __nv_bfloat16 g_Wl[(size_t)HID * KDIM];
__device__ int  g_active[MAX_NODE];
__device__ int  g_count;
__device__ int  g_is64;

// ======================= PTX helpers =======================================
__device__ __forceinline__ uint32_t smem_u32(const void* p) {
    uint32_t a;
    asm("{ .reg .u64 t; cvta.to.shared.u64 t, %1; cvt.u32.u64 %0, t; }"
        : "=r"(a) : "l"(p));
    return a;
}
#define CP16(dst, src) \
    asm volatile("cp.async.cg.shared.global [%0], [%1], 16;" \
        :: "r"(dst), "l"(src) : "memory")
#define CP_COMMIT() asm volatile("cp.async.commit_group;" ::: "memory")
#define CP_WAIT(n)  asm volatile("cp.async.wait_group %0;" :: "n"(n) : "memory")

#define LDSM4(r, a)                                                           \
    asm volatile("ldmatrix.sync.aligned.m8n8.x4.shared.b16 {%0,%1,%2,%3}, [%4];" \
        : "=r"((r)[0]), "=r"((r)[1]), "=r"((r)[2]), "=r"((r)[3]) : "r"(a))

#define MMA16816(c, a, b0, b1)                                                \
    asm volatile("mma.sync.aligned.m16n8k16.row.col.f32.bf16.bf16.f32 "       \
        "{%0,%1,%2,%3}, {%4,%5,%6,%7}, {%8,%9}, {%0,%1,%2,%3};"               \
        : "+f"((c)[0]), "+f"((c)[1]), "+f"((c)[2]), "+f"((c)[3])              \
        : "r"((a)[0]), "r"((a)[1]), "r"((a)[2]), "r"((a)[3]),                 \
          "r"(b0), "r"(b1))

// ===========================================================================
__global__ void detect_reset_kernel(const void* ptrv) {
    g_count = 0;
    // ptr[0]==0; if int64, word[1] is the high half of 0; if int32 it is deg>=1.
    g_is64 = (((const int*)ptrv)[1] == 0) ? 1 : 0;
}

// Split-transpose W [1024,128] fp32 -> g_Wh/g_Wl [128][1024] bf16
__global__ void wprep_kernel(const float* __restrict__ W) {
    int i = blockIdx.x * blockDim.x + threadIdx.x;
    if (i >= KDIM * HID) return;
    int k = i >> 7, n = i & 127;
    float v = W[i];
    __nv_bfloat16 h = __float2bfloat16(v);
    __nv_bfloat16 l = __float2bfloat16(v - __bfloat162float(h));
    g_Wh[(size_t)n * KDIM + k] = h;
    g_Wl[(size_t)n * KDIM + k] = l;
}

// ---------------------------------------------------------------------------
__global__ void compact_history_kernel(const void* __restrict__ hmv,
                                       const float* __restrict__ hb,
                                       float* __restrict__ out,
                                       int dup, int num_node) {
    int w    = (int)((blockIdx.x * blockDim.x + threadIdx.x) >> 5);
    int lane = threadIdx.x & 31;
    if (w >= num_node) return;
    long long m = g_is64 ? ((const long long*)hmv)[w]
                         : (long long)((const int*)hmv)[w];
    if (m != -1LL) {
        float4 v = *(const float4*)(hb + (size_t)w * HID + lane * 4);
        *(float4*)(out + (size_t)w * HID + lane * 4) = v;
        if (dup)
            *(float4*)(out + (size_t)(w + num_node) * HID + lane * 4) = v;
    } else if (lane == 0) {
        int slot = atomicAdd(&g_count, 1);
        g_active[slot] = w;
    }
}

// ---------------------------------------------------------------------------
// Aggregate: TWO warps per active node. Warp half h owns channels
// [h*64, h*64+64); each lane owns 2 channels (float2). 8 relation
// accumulators = 16 regs/lane. 8-deep edge gather pipeline (float2 loads).
__device__ __forceinline__ uint32_t pack_hi(float2 a) {
    __nv_bfloat16 h0 = __float2bfloat16(a.x), h1 = __float2bfloat16(a.y);
    return ((uint32_t)__bfloat16_as_ushort(h1) << 16) | __bfloat16_as_ushort(h0);
}
__device__ __forceinline__ uint32_t pack_lo(float2 a) {
    __nv_bfloat16 h0 = __float2bfloat16(a.x), h1 = __float2bfloat16(a.y);
    __nv_bfloat16 l0 = __float2bfloat16(a.x - __bfloat162float(h0));
    __nv_bfloat16 l1 = __float2bfloat16(a.y - __bfloat162float(h1));
    return ((uint32_t)__bfloat16_as_ushort(l1) << 16) | __bfloat16_as_ushort(l0);
}

#define ACC_CASE2(r, a)                                                       \
    case r: a.x += v_.x; a.y += v_.y; break;

__global__ void aggregate_kernel(const float* __restrict__ x,
                                 const void* __restrict__ ptrv,
                                 const void* __restrict__ idxv,
                                 const void* __restrict__ etv) {
    int w    = (int)((blockIdx.x * blockDim.x + threadIdx.x) >> 5);
    int lane = threadIdx.x & 31;
    int wn   = w >> 1;          // node slot
    int half = w & 1;           // channel half
    if (wn >= g_count) return;
    int is64 = g_is64;
    int node = g_active[wn];

    long long p0, p1;
    if (is64) {
        p0 = ((const long long*)ptrv)[node];
        p1 = ((const long long*)ptrv)[node + 1];
    } else {
        p0 = ((const int*)ptrv)[node];
        p1 = ((const int*)ptrv)[node + 1];
    }
    int deg = (int)(p1 - p0);
    int ch  = half * 64 + lane * 2;     // this lane's channel pair

    float2 a0 = {0,0}, a1 = {0,0}, a2 = {0,0}, a3 = {0,0};
    float2 a4 = {0,0}, a5 = {0,0}, a6 = {0,0}, a7 = {0,0};

    long long s_l = 0; int t_l = 0;
    if (lane < deg) {
        long long e = p0 + lane;
        s_l = is64 ? ((const long long*)idxv)[e]
                   : (long long)((const int*)idxv)[e];
        t_l = is64 ? (int)((const long long*)etv)[e]
                   : ((const int*)etv)[e];
    }
    int dcap = deg < 32 ? deg : 32;

    for (int j0 = 0; j0 < dcap; j0 += 8) {
        float2 v[8]; int tt[8];
        #pragma unroll
        for (int u = 0; u < 8; u++) {
            int j = j0 + u;
            long long src = __shfl_sync(0xffffffffu, s_l, j & 31);
            int      ty   = __shfl_sync(0xffffffffu, t_l, j & 31);
            if (j < dcap) {
                v[u]  = *(const float2*)(x + (size_t)src * HID + ch);
                tt[u] = ty;
            } else {
                v[u] = make_float2(0.f, 0.f);
                tt[u] = NUM_REL;
            }
        }
        #pragma unroll
        for (int u = 0; u < 8; u++) {
            float2 v_ = v[u];
            switch (tt[u]) {
                ACC_CASE2(0, a0) ACC_CASE2(1, a1) ACC_CASE2(2, a2) ACC_CASE2(3, a3)
                ACC_CASE2(4, a4) ACC_CASE2(5, a5) ACC_CASE2(6, a6) ACC_CASE2(7, a7)
                default: break;
            }
        }
    }
    for (long long e = p0 + 32; e < p1; e++) {   // generic tail (unused here)
        long long src = is64 ? ((const long long*)idxv)[e]
                             : (long long)((const int*)idxv)[e];
        int ty = is64 ? (int)((const long long*)etv)[e]
                      : ((const int*)etv)[e];
        float2 v_ = *(const float2*)(x + (size_t)src * HID + ch);
        switch (ty) {
            ACC_CASE2(0, a0) ACC_CASE2(1, a1) ACC_CASE2(2, a2) ACC_CASE2(3, a3)
            ACC_CASE2(4, a4) ACC_CASE2(5, a5) ACC_CASE2(6, a6) ACC_CASE2(7, a7)
            default: break;
        }
    }

    size_t base = (size_t)wn * KDIM + ch;
    __nv_bfloat16* ph = (__nv_bfloat16*)g_Ah;
    __nv_bfloat16* pl = (__nv_bfloat16*)g_Al;
    float2 acc[8] = {a0, a1, a2, a3, a4, a5, a6, a7};
    #pragma unroll
    for (int r = 0; r < 8; r++) {
        *(uint32_t*)(ph + base + r * HID) = pack_hi(acc[r]);
        *(uint32_t*)(pl + base + r * HID) = pack_lo(acc[r]);
    }
}

// ---------------------------------------------------------------------------
// mma.sync GEMM: [count,1024](Ah,Al) @ [1024,128](Wh,Wl), 3-term split.
// CTA 256x128 (512 thr, 16 warps, warp 64x32), k-tile 64, double-buffered.
#define GBM 256
#define GBK 64
#define NT (KDIM / GBK)                // 16 k-tiles
#define TPA (GBM * GBK * 2)            // 32768 bytes per A plane tile
#define TPB (HID * GBK * 2)            // 16384 bytes per B plane tile
#define S_AH 0
#define S_AL TPA
#define S_BH (2 * TPA)
#define S_BL (2 * TPA + TPB)
#define STAGE_B (2 * TPA + 2 * TPB)    // 98304 per stage
#define SMEM_BYTES (2 * STAGE_B)       // 196608

// swizzled byte offset within a [rows][64 bf16] tile (row stride 128B, SW128)
__device__ __forceinline__ uint32_t swz(uint32_t row, uint32_t chunk) {
    return row * 128u + ((chunk ^ (row & 7u)) << 4);
}

__global__ __launch_bounds__(512, 1)
void gemm_mma_kernel(const void* __restrict__ ptrv,
                     float* __restrict__ out,
                     int dup, int num_node) {
    extern __shared__ __align__(1024) char smem[];
    int count = g_count;
    int m0 = blockIdx.x * GBM;
    if (m0 >= count) return;

    uint32_t sb = smem_u32(smem);
    int t = threadIdx.x, wid = t >> 5, lane = t & 31;
    int wm = wid >> 2;                 // 0..3  (m block of 64)
    int wn = wid & 3;                  // 0..3  (n block of 32)

    const __nv_bfloat16* pAh = (const __nv_bfloat16*)g_Ah;
    const __nv_bfloat16* pAl = (const __nv_bfloat16*)g_Al;
    const __nv_bfloat16* pWh = (const __nv_bfloat16*)g_Wh;
    const __nv_bfloat16* pWl = (const __nv_bfloat16*)g_Wl;

    int ltile = lane >> 3, lrow = lane & 7;

    float acc[4][4][4];
    #pragma unroll
    for (int i = 0; i < 4; i++)
        #pragma unroll
        for (int j = 0; j < 4; j++)
            #pragma unroll
            for (int q = 0; q < 4; q++) acc[i][j][q] = 0.f;

    auto load_stage = [&](int kt) {
        uint32_t stg = sb + (kt & 1) * STAGE_B;
        size_t kofs = (size_t)kt * GBK;
        #pragma unroll
        for (int i = 0; i < 4; i++) {
            int id  = t + i * 512;          // 0..2047
            int row = id >> 3;              // 0..255
            int c   = id & 7;
            uint32_t sw = swz(row, c);
            size_t ga = (size_t)(m0 + row) * KDIM + kofs + c * 8;
            CP16(stg + S_AH + sw, pAh + ga);
            CP16(stg + S_AL + sw, pAl + ga);
        }
        #pragma unroll
        for (int i = 0; i < 2; i++) {
            int id  = t + i * 512;          // 0..1023
            int row = id >> 3;              // 0..127
            int c   = id & 7;
            uint32_t sw = swz(row, c);
            size_t gw = (size_t)row * KDIM + kofs + c * 8;
            CP16(stg + S_BH + sw, pWh + gw);
            CP16(stg + S_BL + sw, pWl + gw);
        }
        CP_COMMIT();
    };

    load_stage(0);

    for (int kt = 0; kt < NT; kt++) {
        if (kt + 1 < NT) { load_stage(kt + 1); CP_WAIT(1); }
        else            { CP_WAIT(0); }
        __syncthreads();

        uint32_t stg = sb + (kt & 1) * STAGE_B;
        #pragma unroll
        for (int ks = 0; ks < 4; ks++) {
            int cch = ks * 2 + (ltile >> 1);
            uint32_t bh[2][4], bl[2][4];
            #pragma unroll
            for (int j = 0; j < 2; j++) {
                uint32_t r = wn * 32 + j * 16 + (ltile & 1) * 8 + lrow;
                uint32_t sw = swz(r, (uint32_t)cch);
                LDSM4(bh[j], stg + S_BH + sw);
                LDSM4(bl[j], stg + S_BL + sw);
            }
            #pragma unroll
            for (int mf = 0; mf < 4; mf++) {
                uint32_t ah[4], al[4];
                uint32_t r = wm * 64 + mf * 16 + (ltile & 1) * 8 + lrow;
                uint32_t sw = swz(r, (uint32_t)cch);
                LDSM4(ah, stg + S_AH + sw);
                LDSM4(al, stg + S_AL + sw);
                #pragma unroll
                for (int nf = 0; nf < 4; nf++) {
                    int hj = nf >> 1, ho = nf & 1;
                    MMA16816(acc[mf][nf], ah, bh[hj][ho], bh[hj][ho + 2]);
                    MMA16816(acc[mf][nf], ah, bl[hj][ho], bl[hj][ho + 2]);
                    MMA16816(acc[mf][nf], al, bh[hj][ho], bh[hj][ho + 2]);
                }
            }
        }
        __syncthreads();
    }

    // ---- epilogue: 1/deg scale + scatter (both output halves) ----
    int g  = lane >> 2;
    int tq = lane & 3;
    int is64 = g_is64;
    #pragma unroll
    for (int mf = 0; mf < 4; mf++) {
        int m_lo = m0 + wm * 64 + mf * 16 + g;       // rows g and g+8
        #pragma unroll
        for (int half = 0; half < 2; half++) {
            int m = m_lo + half * 8;
            if (m >= count) continue;
            int node = g_active[m];
            long long d;
            if (is64)
                d = ((const long long*)ptrv)[node + 1] - ((const long long*)ptrv)[node];
            else
                d = (long long)(((const int*)ptrv)[node + 1] - ((const int*)ptrv)[node]);
            float inv = 1.0f / (float)d;
            #pragma unroll
            for (int nf = 0; nf < 4; nf++) {
                float2 v;
                v.x = acc[mf][nf][half * 2 + 0] * inv;
                v.y = acc[mf][nf][half * 2 + 1] * inv;
                size_t co = (size_t)node * HID + wn * 32 + nf * 8 + tq * 2;
                *(float2*)(out + co) = v;
                if (dup)
                    *(float2*)(out + co + (size_t)num_node * HID) = v;
            }
        }
    }
}

// ---------------------------------------------------------------------------
extern "C" void kernel_launch(void* const* d_in, const int* in_sizes, int n_in,
                              void* d_out, int out_size) {
    const float* x  = (const float*)d_in[0];
    const float* W  = (const float*)d_in[1];   // [8,128,128] == [1024,128]
    const void*  pt = d_in[2];
    const void*  ix = d_in[3];
    const void*  et = d_in[4];
    const void*  hm = d_in[5];
    const float* hb = (const float*)d_in[6];
    float* out = (float*)d_out;

    int num_node = in_sizes[0] / HID;
    long long need2 = 2LL * (long long)num_node * HID;
    int dup = ((long long)out_size >= need2) ? 1 : 0;

    cudaFuncSetAttribute(gemm_mma_kernel,
                         cudaFuncAttributeMaxDynamicSharedMemorySize, SMEM_BYTES);

    detect_reset_kernel<<<1, 1>>>(pt);
    wprep_kernel<<<(KDIM * HID + 255) / 256, 256>>>(W);

    int warp_blocks = (num_node * 32 + 255) / 256;
    compact_history_kernel<<<warp_blocks, 256>>>(hm, hb, out, dup, num_node);
    // aggregate: 2 warps per node
    int agg_blocks = (num_node * 2 * 32 + 255) / 256;
    aggregate_kernel<<<agg_blocks, 256>>>(x, pt, ix, et);
    gemm_mma_kernel<<<(num_node + GBM - 1) / GBM, 512, SMEM_BYTES>>>(
        pt, out, dup, num_node);
}

// round 6
// speedup vs baseline: 1.3100x; 1.3100x over previous
#include <cuda_runtime.h>
#include <cuda_fp16.h>
#include <cstdint>

// ---------------------------------------------------------------------------
// RGCN conv with history cache.
//   out[n] = history_buffer[n]                       if history_map[n] != -1
//   out[n] = (1/deg) * sum_r A_r[n] @ W_r            otherwise
// Aggregate per-relation sums into compacted rows (active nodes only), split
// to fp16 hi/lo planes; GEMM = Ah@Wh + Al@Wh (2-term fp16) with mma.sync.
// Round 6: 2-term fp16 GEMM; aggregate gathers staged through smem (cp.async).
// ---------------------------------------------------------------------------

#define MAX_NODE 100000
#define PAD_ROWS (MAX_NODE + 256)
#define HID 128
#define NUM_REL 8
#define KDIM (NUM_REL * HID)   // 1024

__device__ __half g_Ah[(size_t)PAD_ROWS * KDIM];
__device__ __half g_Al[(size_t)PAD_ROWS * KDIM];
__device__ __half g_Wh[(size_t)HID * KDIM];   // [n][k] (K-major)
__device__ int  g_active[MAX_NODE];
__device__ int  g_count;
__device__ int  g_is64;

// ======================= PTX helpers =======================================
__device__ __forceinline__ uint32_t smem_u32(const void* p) {
    uint32_t a;
    asm("{ .reg .u64 t; cvta.to.shared.u64 t, %1; cvt.u32.u64 %0, t; }"
        : "=r"(a) : "l"(p));
    return a;
}
#define CP16(dst, src) \
    asm volatile("cp.async.cg.shared.global [%0], [%1], 16;" \
        :: "r"(dst), "l"(src) : "memory")
#define CP_COMMIT() asm volatile("cp.async.commit_group;" ::: "memory")
#define CP_WAIT(n)  asm volatile("cp.async.wait_group %0;" :: "n"(n) : "memory")
#define CP_WAIT_ALL() asm volatile("cp.async.wait_all;" ::: "memory")

#define LDSM4(r, a)                                                           \
    asm volatile("ldmatrix.sync.aligned.m8n8.x4.shared.b16 {%0,%1,%2,%3}, [%4];" \
        : "=r"((r)[0]), "=r"((r)[1]), "=r"((r)[2]), "=r"((r)[3]) : "r"(a))

#define MMA16816F16(c, a, b0, b1)                                             \
    asm volatile("mma.sync.aligned.m16n8k16.row.col.f32.f16.f16.f32 "         \
        "{%0,%1,%2,%3}, {%4,%5,%6,%7}, {%8,%9}, {%0,%1,%2,%3};"               \
        : "+f"((c)[0]), "+f"((c)[1]), "+f"((c)[2]), "+f"((c)[3])              \
        : "r"((a)[0]), "r"((a)[1]), "r"((a)[2]), "r"((a)[3]),                 \
          "r"(b0), "r"(b1))

// ===========================================================================
__global__ void detect_reset_kernel(const void* ptrv) {
    g_count = 0;
    // ptr[0]==0; if int64, word[1] is the high half of 0; if int32 it is deg>=1.
    g_is64 = (((const int*)ptrv)[1] == 0) ? 1 : 0;
}

// Transpose W [1024,128] fp32 -> g_Wh [128][1024] fp16
__global__ void wprep_kernel(const float* __restrict__ W) {
    int i = blockIdx.x * blockDim.x + threadIdx.x;
    if (i >= KDIM * HID) return;
    int k = i >> 7, n = i & 127;
    g_Wh[(size_t)n * KDIM + k] = __float2half(W[i]);
}

// ---------------------------------------------------------------------------
__global__ void compact_history_kernel(const void* __restrict__ hmv,
                                       const float* __restrict__ hb,
                                       float* __restrict__ out,
                                       int dup, int num_node) {
    int w    = (int)((blockIdx.x * blockDim.x + threadIdx.x) >> 5);
    int lane = threadIdx.x & 31;
    if (w >= num_node) return;
    long long m = g_is64 ? ((const long long*)hmv)[w]
                         : (long long)((const int*)hmv)[w];
    if (m != -1LL) {
        float4 v = *(const float4*)(hb + (size_t)w * HID + lane * 4);
        *(float4*)(out + (size_t)w * HID + lane * 4) = v;
        if (dup)
            *(float4*)(out + (size_t)(w + num_node) * HID + lane * 4) = v;
    } else if (lane == 0) {
        int slot = atomicAdd(&g_count, 1);
        g_active[slot] = w;
    }
}

// ---------------------------------------------------------------------------
// Aggregate: one warp per node; gathers staged through smem via cp.async
// (MLP=16 with no register gather buffers). Lane owns 4 channels.
__device__ __forceinline__ void split_store_h(float4 a, size_t off) {
    __half h0 = __float2half(a.x), h1 = __float2half(a.y);
    __half h2 = __float2half(a.z), h3 = __float2half(a.w);
    __half l0 = __float2half(a.x - __half2float(h0));
    __half l1 = __float2half(a.y - __half2float(h1));
    __half l2 = __float2half(a.z - __half2float(h2));
    __half l3 = __float2half(a.w - __half2float(h3));
    uint2 uh, ul;
    uh.x = ((uint32_t)__half_as_ushort(h1) << 16) | __half_as_ushort(h0);
    uh.y = ((uint32_t)__half_as_ushort(h3) << 16) | __half_as_ushort(h2);
    ul.x = ((uint32_t)__half_as_ushort(l1) << 16) | __half_as_ushort(l0);
    ul.y = ((uint32_t)__half_as_ushort(l3) << 16) | __half_as_ushort(l2);
    *(uint2*)((__half*)g_Ah + off) = uh;
    *(uint2*)((__half*)g_Al + off) = ul;
}

#define ACC_CASE(r, a)                                                        \
    case r: a.x += v_.x; a.y += v_.y; a.z += v_.z; a.w += v_.w; break;

#define AGG_CHUNK 16
#define AGG_ROWB  (AGG_CHUNK * HID)     // floats per warp buffer

__global__ __launch_bounds__(256)
void aggregate_kernel(const float* __restrict__ x,
                      const void* __restrict__ ptrv,
                      const void* __restrict__ idxv,
                      const void* __restrict__ etv) {
    extern __shared__ float sbuf[];     // 8 warps * 16 rows * 512B = 64 KB
    int w    = (int)((blockIdx.x * blockDim.x + threadIdx.x) >> 5);
    int lane = threadIdx.x & 31;
    if (w >= g_count) return;
    int is64 = g_is64;
    int node = g_active[w];

    long long p0, p1;
    if (is64) {
        p0 = ((const long long*)ptrv)[node];
        p1 = ((const long long*)ptrv)[node + 1];
    } else {
        p0 = ((const int*)ptrv)[node];
        p1 = ((const int*)ptrv)[node + 1];
    }
    int deg = (int)(p1 - p0);

    float*   mybuf  = sbuf + (size_t)(threadIdx.x >> 5) * AGG_ROWB;
    uint32_t sm     = smem_u32(mybuf);

    float4 a0 = {0,0,0,0}, a1 = {0,0,0,0}, a2 = {0,0,0,0}, a3 = {0,0,0,0};
    float4 a4 = {0,0,0,0}, a5 = {0,0,0,0}, a6 = {0,0,0,0}, a7 = {0,0,0,0};

    for (long long c0 = p0; c0 < p1; c0 += AGG_CHUNK) {
        int n = (int)((p1 - c0) < AGG_CHUNK ? (p1 - c0) : AGG_CHUNK);
        long long s_l = 0; int t_l = 0;
        if (lane < n) {
            long long e = c0 + lane;
            s_l = is64 ? ((const long long*)idxv)[e]
                       : (long long)((const int*)idxv)[e];
            t_l = is64 ? (int)((const long long*)etv)[e]
                       : ((const int*)etv)[e];
        }
        if (n == AGG_CHUNK) {
            #pragma unroll
            for (int e = 0; e < AGG_CHUNK; e++) {
                long long src = __shfl_sync(0xffffffffu, s_l, e);
                CP16(sm + (uint32_t)(e * 512 + lane * 16),
                     x + (size_t)src * HID + lane * 4);
            }
            CP_WAIT_ALL();
            __syncwarp();
            #pragma unroll
            for (int e = 0; e < AGG_CHUNK; e++) {
                int ty = __shfl_sync(0xffffffffu, t_l, e);
                float4 v_ = *(const float4*)(mybuf + e * HID + lane * 4);
                switch (ty) {
                    ACC_CASE(0, a0) ACC_CASE(1, a1) ACC_CASE(2, a2) ACC_CASE(3, a3)
                    ACC_CASE(4, a4) ACC_CASE(5, a5) ACC_CASE(6, a6) ACC_CASE(7, a7)
                    default: break;
                }
            }
        } else {
            for (int e = 0; e < n; e++) {
                long long src = __shfl_sync(0xffffffffu, s_l, e);
                CP16(sm + (uint32_t)(e * 512 + lane * 16),
                     x + (size_t)src * HID + lane * 4);
            }
            CP_WAIT_ALL();
            __syncwarp();
            for (int e = 0; e < n; e++) {
                int ty = __shfl_sync(0xffffffffu, t_l, e);
                float4 v_ = *(const float4*)(mybuf + e * HID + lane * 4);
                switch (ty) {
                    ACC_CASE(0, a0) ACC_CASE(1, a1) ACC_CASE(2, a2) ACC_CASE(3, a3)
                    ACC_CASE(4, a4) ACC_CASE(5, a5) ACC_CASE(6, a6) ACC_CASE(7, a7)
                    default: break;
                }
            }
        }
        __syncwarp();
    }

    size_t base = (size_t)w * KDIM + lane * 4;
    split_store_h(a0, base + 0 * HID);  split_store_h(a1, base + 1 * HID);
    split_store_h(a2, base + 2 * HID);  split_store_h(a3, base + 3 * HID);
    split_store_h(a4, base + 4 * HID);  split_store_h(a5, base + 5 * HID);
    split_store_h(a6, base + 6 * HID);  split_store_h(a7, base + 7 * HID);
}
#define AGG_SMEM (8 * AGG_ROWB * 4)     // 65536 bytes

// ---------------------------------------------------------------------------
// mma.sync GEMM: [count,1024](Ah,Al) @ [1024,128](Wh), 2-term fp16 split.
// CTA 256x128 (512 thr, 16 warps, warp 64x32), k-tile 64, double-buffered.
#define GBM 256
#define GBK 64
#define NT (KDIM / GBK)                // 16 k-tiles
#define TPA (GBM * GBK * 2)            // 32768 bytes per A plane tile
#define TPB (HID * GBK * 2)            // 16384 bytes per B plane tile
#define S_AH 0
#define S_AL TPA
#define S_BH (2 * TPA)
#define STAGE_B (2 * TPA + TPB)        // 81920 per stage
#define SMEM_BYTES (2 * STAGE_B)       // 163840

// swizzled byte offset within a [rows][64 f16] tile (row stride 128B, SW128)
__device__ __forceinline__ uint32_t swz(uint32_t row, uint32_t chunk) {
    return row * 128u + ((chunk ^ (row & 7u)) << 4);
}

__global__ __launch_bounds__(512, 1)
void gemm_mma_kernel(const void* __restrict__ ptrv,
                     float* __restrict__ out,
                     int dup, int num_node) {
    extern __shared__ __align__(1024) char smem[];
    int count = g_count;
    int m0 = blockIdx.x * GBM;
    if (m0 >= count) return;

    uint32_t sb = smem_u32(smem);
    int t = threadIdx.x, wid = t >> 5, lane = t & 31;
    int wm = wid >> 2;                 // 0..3  (m block of 64)
    int wn = wid & 3;                  // 0..3  (n block of 32)

    const __half* pAh = (const __half*)g_Ah;
    const __half* pAl = (const __half*)g_Al;
    const __half* pWh = (const __half*)g_Wh;

    int ltile = lane >> 3, lrow = lane & 7;

    float acc[4][4][4];
    #pragma unroll
    for (int i = 0; i < 4; i++)
        #pragma unroll
        for (int j = 0; j < 4; j++)
            #pragma unroll
            for (int q = 0; q < 4; q++) acc[i][j][q] = 0.f;

    auto load_stage = [&](int kt) {
        uint32_t stg = sb + (kt & 1) * STAGE_B;
        size_t kofs = (size_t)kt * GBK;
        #pragma unroll
        for (int i = 0; i < 4; i++) {
            int id  = t + i * 512;          // 0..2047
            int row = id >> 3;              // 0..255
            int c   = id & 7;
            uint32_t sw = swz(row, c);
            size_t ga = (size_t)(m0 + row) * KDIM + kofs + c * 8;
            CP16(stg + S_AH + sw, pAh + ga);
            CP16(stg + S_AL + sw, pAl + ga);
        }
        #pragma unroll
        for (int i = 0; i < 2; i++) {
            int id  = t + i * 512;          // 0..1023
            int row = id >> 3;              // 0..127
            int c   = id & 7;
            uint32_t sw = swz(row, c);
            size_t gw = (size_t)row * KDIM + kofs + c * 8;
            CP16(stg + S_BH + sw, pWh + gw);
        }
        CP_COMMIT();
    };

    load_stage(0);

    for (int kt = 0; kt < NT; kt++) {
        if (kt + 1 < NT) { load_stage(kt + 1); CP_WAIT(1); }
        else            { CP_WAIT(0); }
        __syncthreads();

        uint32_t stg = sb + (kt & 1) * STAGE_B;
        #pragma unroll
        for (int ks = 0; ks < 4; ks++) {
            int cch = ks * 2 + (ltile >> 1);
            uint32_t bh[2][4];
            #pragma unroll
            for (int j = 0; j < 2; j++) {
                uint32_t r = wn * 32 + j * 16 + (ltile & 1) * 8 + lrow;
                uint32_t sw = swz(r, (uint32_t)cch);
                LDSM4(bh[j], stg + S_BH + sw);
            }
            #pragma unroll
            for (int mf = 0; mf < 4; mf++) {
                uint32_t ah[4], al[4];
                uint32_t r = wm * 64 + mf * 16 + (ltile & 1) * 8 + lrow;
                uint32_t sw = swz(r, (uint32_t)cch);
                LDSM4(ah, stg + S_AH + sw);
                LDSM4(al, stg + S_AL + sw);
                #pragma unroll
                for (int nf = 0; nf < 4; nf++) {
                    int hj = nf >> 1, ho = nf & 1;
                    MMA16816F16(acc[mf][nf], ah, bh[hj][ho], bh[hj][ho + 2]);
                }
                #pragma unroll
                for (int nf = 0; nf < 4; nf++) {
                    int hj = nf >> 1, ho = nf & 1;
                    MMA16816F16(acc[mf][nf], al, bh[hj][ho], bh[hj][ho + 2]);
                }
            }
        }
        __syncthreads();
    }

    // ---- epilogue: 1/deg scale + scatter (both output halves) ----
    int g  = lane >> 2;
    int tq = lane & 3;
    int is64 = g_is64;
    #pragma unroll
    for (int mf = 0; mf < 4; mf++) {
        int m_lo = m0 + wm * 64 + mf * 16 + g;       // rows g and g+8
        #pragma unroll
        for (int half = 0; half < 2; half++) {
            int m = m_lo + half * 8;
            if (m >= count) continue;
            int node = g_active[m];
            long long d;
            if (is64)
                d = ((const long long*)ptrv)[node + 1] - ((const long long*)ptrv)[node];
            else
                d = (long long)(((const int*)ptrv)[node + 1] - ((const int*)ptrv)[node]);
            float inv = 1.0f / (float)d;
            #pragma unroll
            for (int nf = 0; nf < 4; nf++) {
                float2 v;
                v.x = acc[mf][nf][half * 2 + 0] * inv;
                v.y = acc[mf][nf][half * 2 + 1] * inv;
                size_t co = (size_t)node * HID + wn * 32 + nf * 8 + tq * 2;
                *(float2*)(out + co) = v;
                if (dup)
                    *(float2*)(out + co + (size_t)num_node * HID) = v;
            }
        }
    }
}

// ---------------------------------------------------------------------------
extern "C" void kernel_launch(void* const* d_in, const int* in_sizes, int n_in,
                              void* d_out, int out_size) {
    const float* x  = (const float*)d_in[0];
    const float* W  = (const float*)d_in[1];   // [8,128,128] == [1024,128]
    const void*  pt = d_in[2];
    const void*  ix = d_in[3];
    const void*  et = d_in[4];
    const void*  hm = d_in[5];
    const float* hb = (const float*)d_in[6];
    float* out = (float*)d_out;

    int num_node = in_sizes[0] / HID;
    long long need2 = 2LL * (long long)num_node * HID;
    int dup = ((long long)out_size >= need2) ? 1 : 0;

    cudaFuncSetAttribute(gemm_mma_kernel,
                         cudaFuncAttributeMaxDynamicSharedMemorySize, SMEM_BYTES);
    cudaFuncSetAttribute(aggregate_kernel,
                         cudaFuncAttributeMaxDynamicSharedMemorySize, AGG_SMEM);

    detect_reset_kernel<<<1, 1>>>(pt);
    wprep_kernel<<<(KDIM * HID + 255) / 256, 256>>>(W);

    int warp_blocks = (num_node * 32 + 255) / 256;
    compact_history_kernel<<<warp_blocks, 256>>>(hm, hb, out, dup, num_node);
    aggregate_kernel<<<warp_blocks, 256, AGG_SMEM>>>(x, pt, ix, et);
    gemm_mma_kernel<<<(num_node + GBM - 1) / GBM, 512, SMEM_BYTES>>>(
        pt, out, dup, num_node);
}